// round 9
// baseline (speedup 1.0000x reference)
#include <cuda_runtime.h>

#define IMG 512
#define TW 64
#define TH 32
#define KS 11
#define HALO 5
#define COLS 74              /* TW + 2*HALO */
#define S4 75                /* float4 row stride: 300 words -> conflict-free LDS.128 */
#define RG 8                 /* output rows per vertical task */
#define NROWS (RG + KS - 1)  /* 18 input rows per task */
#define NTASK (COLS*(TH/RG)) /* 296 */
#define NTHREADS 256
#define NBLK (8*16*64)
/* smem: s_all 32*75*16 = 38400 B -> 4 CTAs/SM */
#define SMEM_BYTES (TH*S4*16)

typedef unsigned long long u64;

__device__ double g_accum;
__device__ unsigned int g_done;
__device__ float g_wv[2][KS];
__device__ float g_wh[2][KS];

__device__ __forceinline__ u64 pack2(float x, float y) {
    u64 r; asm("mov.b64 %0, {%1,%2};" : "=l"(r) : "f"(x), "f"(y)); return r;
}
__device__ __forceinline__ void unpack2(u64 v, float& x, float& y) {
    asm("mov.b64 {%0,%1}, %2;" : "=f"(x), "=f"(y) : "l"(v));
}
__device__ __forceinline__ u64 fma2(u64 a, u64 b, u64 c) {
    u64 d; asm("fma.rn.f32x2 %0, %1, %2, %3;" : "=l"(d) : "l"(a), "l"(b), "l"(c)); return d;
}

/* Gaussian symmetry w[k] == w[10-k] (bit-exact: k2 = g outer g) */
#define WIDX(k) ((k) < 6 ? (k) : 10 - (k))

// Rank-1 factor reconstruction, parallel: warp 0 -> ch 0, warp 1 -> ch 1.
__global__ void prep_kernel(const float* __restrict__ kern) {
    int tid = threadIdx.x;
    if (tid == 0) { g_accum = 0.0; g_done = 0u; }
    if (tid < 64) {
        int ch = tid >> 5, lane = tid & 31;
        const float* kc = kern + ch * KS * KS;
        float s = 0.f;
        if (lane < KS) {
            #pragma unroll
            for (int j = 0; j < KS; j++) s += kc[lane * KS + j];       // row sums
        } else if (lane < 2 * KS) {
            #pragma unroll
            for (int j = 0; j < KS; j++) s += kc[j * KS + lane - KS];  // col sums
        }
        float contrib = (lane < KS) ? s : 0.f;
        #pragma unroll
        for (int o = 16; o > 0; o >>= 1) contrib += __shfl_xor_sync(0xffffffffu, contrib, o);
        if (lane < KS)           g_wv[ch][lane] = s;
        else if (lane < 2 * KS)  g_wh[ch][lane - KS] = s / contrib;
    }
}

extern __shared__ ulonglong2 smem_dyn[];

/* accumulate one input px (vx,vy) into RG row accumulators:
   stream u = (x, y), stream q = (x^2 + y^2, x*y) */
__device__ __forceinline__ void vaccum(float vx, float vy, int tt,
                                       const u64* __restrict__ wv2,
                                       u64* a1, u64* aq) {
    u64 u = pack2(vx, vy);
    float s2  = fmaf(vy, vy, vx * vx);
    float pxy = vx * vy;
    u64 q = pack2(s2, pxy);
    #pragma unroll
    for (int i = 0; i < RG; i++) {
        int k = tt - i;
        if (k >= 0 && k < KS) {
            int wi = WIDX(k);
            a1[i] = fma2(wv2[wi], u, a1[i]);
            aq[i] = fma2(wv2[wi], q, aq[i]);
        }
    }
}

__global__ __launch_bounds__(NTHREADS, 4)
void ssim_main(const float* __restrict__ x, const float* __restrict__ y,
               float* __restrict__ out) {
    ulonglong2* s_all = smem_dyn;             // [TH][S4] {(sum_x,sum_y),(sum_q,sum_xy)}

    const int tid = threadIdx.x;
    const int plane = blockIdx.z;             // 64 = 32 batch * 2 chan (NCHW)
    const int ch = plane & 1;
    const int oh0 = blockIdx.y * TH;
    const int ow0 = blockIdx.x * TW;
    const float* xp = x + (size_t)plane * IMG * IMG;
    const float* yp = y + (size_t)plane * IMG * IMG;

    u64 wv2[6];
    #pragma unroll
    for (int k = 0; k < 6; k++) { float w = __ldg(&g_wv[ch][k]); wv2[k] = pack2(w, w); }

    // block-uniform interior test (tile + halo fully inside image)
    const bool interior = (blockIdx.x >= 1) & (blockIdx.x <= 6) &
                          (blockIdx.y >= 1) & (blockIdx.y <= 14);

    // ---- stage 1: vertical conv straight from global ----
    if (interior) {
        for (int t = tid; t < NTASK; t += NTHREADS) {
            int rgi = t / COLS;
            int col = t - rgi * COLS;
            int rg = rgi * RG;
            int r0 = oh0 + rg - HALO;
            const float* xb = xp + (ptrdiff_t)r0 * IMG + (ow0 + col - HALO);
            const float* yb = yp + (ptrdiff_t)r0 * IMG + (ow0 + col - HALO);

            u64 a1[RG], aq[RG];
            #pragma unroll
            for (int i = 0; i < RG; i++) { a1[i] = 0ull; aq[i] = 0ull; }

            #pragma unroll
            for (int tt = 0; tt < NROWS; tt++)   // 18 rows, unpredicated
                vaccum(__ldg(xb + tt * IMG), __ldg(yb + tt * IMG), tt, wv2, a1, aq);

            #pragma unroll
            for (int i = 0; i < RG; i++)
                s_all[(rg + i) * S4 + col] = make_ulonglong2(a1[i], aq[i]);   // STS.128
        }
    } else {
        for (int t = tid; t < NTASK; t += NTHREADS) {
            int rgi = t / COLS;
            int col = t - rgi * COLS;
            int rg = rgi * RG;
            int gc = ow0 + col - HALO;
            bool colok = (unsigned)gc < (unsigned)IMG;
            int r0 = oh0 + rg - HALO;
            const float* xb = xp + (ptrdiff_t)r0 * IMG + gc;
            const float* yb = yp + (ptrdiff_t)r0 * IMG + gc;

            u64 a1[RG], aq[RG];
            #pragma unroll
            for (int i = 0; i < RG; i++) { a1[i] = 0ull; aq[i] = 0ull; }

            #pragma unroll
            for (int tt = 0; tt < NROWS; tt++) {
                int gr = r0 + tt;
                float vx = 0.f, vy = 0.f;
                if (colok && (unsigned)gr < (unsigned)IMG) {
                    vx = __ldg(xb + tt * IMG);
                    vy = __ldg(yb + tt * IMG);
                }
                vaccum(vx, vy, tt, wv2, a1, aq);
            }
            #pragma unroll
            for (int i = 0; i < RG; i++)
                s_all[(rg + i) * S4 + col] = make_ulonglong2(a1[i], aq[i]);
        }
    }

    __syncthreads();

    // ---- stage 2: horizontal conv, single 8-px pass per thread ----
    u64 wh2[6];
    #pragma unroll
    for (int k = 0; k < 6; k++) { float w = __ldg(&g_wh[ch][k]); wh2[k] = pack2(w, w); }

    const int row = tid & 31;      // lanes span rows -> phase-conflict-free LDS.128
    const int c0 = (tid >> 5) * 8;
    const float C1 = 1e-4f, C2 = 9e-4f;
    float lsum = 0.f;

    u64 h1[8], hq[8];
    #pragma unroll
    for (int p = 0; p < 8; p++) { h1[p] = 0ull; hq[p] = 0ull; }

    #pragma unroll
    for (int j = 0; j < 8 + KS - 1; j++) {      // 18 input cols, one LDS.128 each
        ulonglong2 b = s_all[row * S4 + c0 + j];
        #pragma unroll
        for (int p = 0; p < 8; p++) {
            int k = j - p;
            if (k >= 0 && k < KS) {
                int wi = WIDX(k);
                h1[p] = fma2(wh2[wi], b.x, h1[p]);
                hq[p] = fma2(wh2[wi], b.y, hq[p]);
            }
        }
    }

    // ---- epilogue: SSIM per pixel ----
    #pragma unroll
    for (int p = 0; p < 8; p++) {
        float mux, muy; unpack2(h1[p], mux, muy);
        float es, exy;  unpack2(hq[p], es, exy);     // es = E[x^2+y^2]
        float muxy = mux * muy;
        float sxy  = fmaf(-mux, muy, exy);           // E[xy] - mux*muy
        float na   = fmaf(muxy, 2.0f, C1);
        float nb   = fmaf(sxy,  2.0f, C2);
        float m2   = fmaf(mux, mux, muy * muy);      // mux^2 + muy^2
        float dena = m2 + C1;
        float denb = (es - m2) + C2;                 // (sx + sy) + C2
        lsum += __fdividef(na * nb, dena * denb);
    }

    // ---- reduction: warp -> block -> global atomic -> last-block finalize ----
    #pragma unroll
    for (int o = 16; o > 0; o >>= 1) lsum += __shfl_xor_sync(0xffffffffu, lsum, o);
    __shared__ float wsum[NTHREADS / 32];
    if ((tid & 31) == 0) wsum[tid >> 5] = lsum;
    __syncthreads();
    if (tid == 0) {
        float b = 0.f;
        #pragma unroll
        for (int w = 0; w < NTHREADS / 32; w++) b += wsum[w];
        atomicAdd(&g_accum, (double)b);
        __threadfence();
        unsigned prev = atomicAdd(&g_done, 1u);
        if (prev == (unsigned)(NBLK - 1)) {          // last block finalizes
            __threadfence();
            double total = atomicAdd(&g_accum, 0.0); // coherent L2 read
            out[0] = 1.0f - (float)(total * (1.0 / (32.0 * 2.0 * 512.0 * 512.0)));
        }
    }
}

extern "C" void kernel_launch(void* const* d_in, const int* in_sizes, int n_in,
                              void* d_out, int out_size) {
    const float* x = (const float*)d_in[0];
    const float* y = (const float*)d_in[1];
    const float* kern = (const float*)d_in[2];
    float* out = (float*)d_out;

    prep_kernel<<<1, 64>>>(kern);
    dim3 grid(IMG / TW, IMG / TH, 64);
    ssim_main<<<grid, NTHREADS, SMEM_BYTES>>>(x, y, out);
}